// round 9
// baseline (speedup 1.0000x reference)
#include <cuda_runtime.h>

#define NN 50000
#define IC 512
#define OC 128
#define NE 1600000
#define NB 196   // scan blocks: 196*256 = 50176 >= NN

typedef unsigned long long ull;

// ---------------------------------------------------------------------------
// Scratch (static __device__ — no allocation in kernel_launch)
__device__ int   g_deg[NN];
__device__ int   g_off[NN + 1];   // CSR row offsets (by dst)
__device__ int   g_cur[NN];       // scatter cursors
__device__ int   g_csrc[NE];      // CSR column = src node per edge
__device__ float g_dis[NN];
__device__ int   g_bsum[NB];      // per-block degree sums
__device__ int   g_bscan[NB + 1]; // exclusive scan of block sums
__device__ float g_y[(size_t)NN * OC];          // x @ W_enc (UNSCALED)
__device__ float g_h[(size_t)(NN + 32) * OC];   // relu(dis*(gather) + b), padded

// k-pair weights, lane-contiguous layout: [kp][j][cg] of ull2.
__device__ ulonglong2 g_WpE[256 * 4 * 16];
__device__ ulonglong2 g_WpD[64 * 4 * 64];

__device__ __forceinline__ void fma2(ull& d, ull a, ull b) {
    asm("fma.rn.f32x2 %0, %1, %2, %0;" : "+l"(d) : "l"(a), "l"(b));
}
__device__ __forceinline__ float2 up2(ull a) {
    float2 r;
    asm("mov.b64 {%0, %1}, %2;" : "=f"(r.x), "=f"(r.y) : "l"(a));
    return r;
}

// ---------------------------------------------------------------------------
// K0: zero deg
__global__ void k_zero() {
    int i = blockIdx.x * blockDim.x + threadIdx.x;
    if (i < NN) g_deg[i] = 0;
}

// K1: dst-degree histogram
__global__ void k_deg(const int* __restrict__ ei) {
    int i = blockIdx.x * blockDim.x + threadIdx.x;
    if (i < NE) atomicAdd(&g_deg[ei[NE + i]], 1);
}

// Scan stage 1: per-block sums of 256 degrees
__global__ __launch_bounds__(256) void k_bsum() {
    __shared__ int ss[8];
    int i = blockIdx.x * 256 + threadIdx.x;
    int v = (i < NN) ? g_deg[i] : 0;
#pragma unroll
    for (int o = 16; o; o >>= 1) v += __shfl_xor_sync(0xffffffffu, v, o);
    if ((threadIdx.x & 31) == 0) ss[threadIdx.x >> 5] = v;
    __syncthreads();
    if (threadIdx.x == 0) {
        int s = 0;
#pragma unroll
        for (int w = 0; w < 8; w++) s += ss[w];
        g_bsum[blockIdx.x] = s;
    }
}

// Scan stage 2: one block exclusive-scans NB block sums
__global__ __launch_bounds__(256) void k_bscan() {
    __shared__ int sc[256];
    int t = threadIdx.x;
    int v = (t < NB) ? g_bsum[t] : 0;
    sc[t] = v;
    __syncthreads();
    for (int off = 1; off < 256; off <<= 1) {
        int u = (t >= off) ? sc[t - off] : 0;
        __syncthreads();
        sc[t] += u;
        __syncthreads();
    }
    if (t < NB) g_bscan[t] = sc[t] - v;   // exclusive
    if (t == NB - 1) g_bscan[NB] = sc[t];
}

// Scan stage 3: per-block scan of degrees + global base -> off/cur/dis
__global__ __launch_bounds__(256) void k_off() {
    __shared__ int sc[256];
    int t = threadIdx.x;
    int i = blockIdx.x * 256 + t;
    int d = (i < NN) ? g_deg[i] : 0;
    sc[t] = d;
    __syncthreads();
    for (int off = 1; off < 256; off <<= 1) {
        int u = (t >= off) ? sc[t - off] : 0;
        __syncthreads();
        sc[t] += u;
        __syncthreads();
    }
    if (i < NN) {
        int base = g_bscan[blockIdx.x] + sc[t] - d;  // exclusive
        g_off[i] = base;
        g_cur[i] = base;
        g_dis[i] = rsqrtf((float)(d + 1));
        if (i == NN - 1) g_off[NN] = base + d;
    }
}

// K3: scatter edges into CSR (order within a row is irrelevant for a sum)
__global__ void k_scatter(const int* __restrict__ ei) {
    int i = blockIdx.x * blockDim.x + threadIdx.x;
    if (i >= NE) return;
    int s = ei[i];
    int d = ei[NE + i];
    int p = atomicAdd(&g_cur[d], 1);
    g_csrc[p] = s;
}

// K_prep: build lane-contiguous k-pair weight layouts
__global__ void k_prep(const float* __restrict__ We, const float* __restrict__ Wd) {
    int i = blockIdx.x * blockDim.x + threadIdx.x;
    if (i < 256 * 4 * 16) {  // enc
        int kp = i >> 6, j = (i >> 4) & 3, cg = i & 15;
        int c = cg * 8 + 2 * j;
        float4 v;
        v.x = We[(2 * kp) * OC + c];
        v.y = We[(2 * kp + 1) * OC + c];
        v.z = We[(2 * kp) * OC + c + 1];
        v.w = We[(2 * kp + 1) * OC + c + 1];
        ((float4*)g_WpE)[i] = v;
    }
    if (i < 64 * 4 * 64) {  // dec
        int kp = i >> 8, j = (i >> 6) & 3, cg = i & 63;
        int c = cg * 8 + 2 * j;
        float4 v;
        v.x = Wd[(2 * kp) * IC + c];
        v.y = Wd[(2 * kp + 1) * IC + c];
        v.z = Wd[(2 * kp) * IC + c + 1];
        v.w = Wd[(2 * kp + 1) * IC + c + 1];
        ((float4*)g_WpD)[i] = v;
    }
}

// ---------------------------------------------------------------------------
// K4: y = x @ W_enc (UNSCALED) via packed f32x2 FMA, K-paired.
// 64 rows/block, 256 threads. No dependency on graph build -> overlappable.
__global__ __launch_bounds__(256) void k_gemm1(const float* __restrict__ x) {
    const int tid = threadIdx.x;
    const int warp = tid >> 5, lane = tid & 31;
    const int cg = lane & 15, rg = lane >> 4;
    const int row0 = blockIdx.x * 64 + warp * 8 + rg * 4;

    const ulonglong2* __restrict__ xq = (const ulonglong2*)x;

    int r[4];
#pragma unroll
    for (int m = 0; m < 4; m++) r[m] = min(row0 + m, NN - 1);

    ull acc[4][8];
#pragma unroll
    for (int m = 0; m < 4; m++)
#pragma unroll
        for (int j = 0; j < 8; j++) acc[m][j] = 0ull;

    for (int kp = 0; kp < 256; kp += 4) {
        ulonglong2 xv[4][2];
#pragma unroll
        for (int m = 0; m < 4; m++) {
            size_t base = (size_t)r[m] * 128 + (kp >> 1);
            xv[m][0] = xq[base];
            xv[m][1] = xq[base + 1];
        }
#pragma unroll
        for (int kp2 = 0; kp2 < 4; kp2++) {
            const ulonglong2* wbase = &g_WpE[(kp + kp2) * 64 + cg];
            ulonglong2 w0 = wbase[0];
            ulonglong2 w1 = wbase[16];
            ulonglong2 w2 = wbase[32];
            ulonglong2 w3 = wbase[48];
#pragma unroll
            for (int m = 0; m < 4; m++) {
                ull xm = (kp2 & 1) ? xv[m][kp2 >> 1].y : xv[m][kp2 >> 1].x;
                fma2(acc[m][0], xm, w0.x);
                fma2(acc[m][1], xm, w0.y);
                fma2(acc[m][2], xm, w1.x);
                fma2(acc[m][3], xm, w1.y);
                fma2(acc[m][4], xm, w2.x);
                fma2(acc[m][5], xm, w2.y);
                fma2(acc[m][6], xm, w3.x);
                fma2(acc[m][7], xm, w3.y);
            }
        }
    }

#pragma unroll
    for (int m = 0; m < 4; m++) {
        int row = row0 + m;
        if (row >= NN) continue;
        float v[8];
#pragma unroll
        for (int j = 0; j < 8; j++) {
            float2 p = up2(acc[m][j]);
            v[j] = p.x + p.y;
        }
        float4* o = (float4*)(g_y + (size_t)row * OC + cg * 8);
        o[0] = make_float4(v[0], v[1], v[2], v[3]);
        o[1] = make_float4(v[4], v[5], v[6], v[7]);
    }
}

// ---------------------------------------------------------------------------
// K5: gather + epilogue, one warp per node, high occupancy.
// h[n] = relu(dis[n]*(y[n]*dis[n] + sum_{src} y[src]*dis[src]) + b)
__global__ __launch_bounds__(256) void k_gather(const float* __restrict__ b) {
    const int warp = blockIdx.x * 8 + (threadIdx.x >> 5);
    if (warp >= NN) return;
    const int lane = threadIdx.x & 31;
    const int n = warp;

    const float4* __restrict__ y4 = (const float4*)g_y;

    float dn = g_dis[n];
    float4 a = y4[(size_t)n * 32 + lane];  // self loop: y[n] * dis[n]
    a.x *= dn; a.y *= dn; a.z *= dn; a.w *= dn;

    int e = g_off[n], end = g_off[n + 1];
    for (; e + 4 <= end; e += 4) {
        int s0 = g_csrc[e],     s1 = g_csrc[e + 1];
        int s2 = g_csrc[e + 2], s3 = g_csrc[e + 3];
        float d0 = g_dis[s0], d1 = g_dis[s1];
        float d2 = g_dis[s2], d3 = g_dis[s3];
        float4 v0 = y4[(size_t)s0 * 32 + lane];
        float4 v1 = y4[(size_t)s1 * 32 + lane];
        float4 v2 = y4[(size_t)s2 * 32 + lane];
        float4 v3 = y4[(size_t)s3 * 32 + lane];
        a.x = fmaf(v0.x, d0, a.x); a.y = fmaf(v0.y, d0, a.y);
        a.z = fmaf(v0.z, d0, a.z); a.w = fmaf(v0.w, d0, a.w);
        a.x = fmaf(v1.x, d1, a.x); a.y = fmaf(v1.y, d1, a.y);
        a.z = fmaf(v1.z, d1, a.z); a.w = fmaf(v1.w, d1, a.w);
        a.x = fmaf(v2.x, d2, a.x); a.y = fmaf(v2.y, d2, a.y);
        a.z = fmaf(v2.z, d2, a.z); a.w = fmaf(v2.w, d2, a.w);
        a.x = fmaf(v3.x, d3, a.x); a.y = fmaf(v3.y, d3, a.y);
        a.z = fmaf(v3.z, d3, a.z); a.w = fmaf(v3.w, d3, a.w);
    }
    for (; e < end; e++) {
        int s = g_csrc[e];
        float ds = g_dis[s];
        float4 v = y4[(size_t)s * 32 + lane];
        a.x = fmaf(v.x, ds, a.x); a.y = fmaf(v.y, ds, a.y);
        a.z = fmaf(v.z, ds, a.z); a.w = fmaf(v.w, ds, a.w);
    }
    const float4 b4 = ((const float4*)b)[lane];
    float4 h;
    h.x = fmaxf(fmaf(dn, a.x, b4.x), 0.f);
    h.y = fmaxf(fmaf(dn, a.y, b4.y), 0.f);
    h.z = fmaxf(fmaf(dn, a.z, b4.z), 0.f);
    h.w = fmaxf(fmaf(dn, a.w, b4.w), 0.f);
    ((float4*)g_h)[(size_t)n * 32 + lane] = h;
}

// ---------------------------------------------------------------------------
// K6: decode GEMM (f32x2, K-paired) + softmax from precomputed h.
// 32 nodes/block, 512 threads. cg = tid&63 -> cols cg*8..+7; rg = tid>>6.
__global__ __launch_bounds__(512) void k_dec(float* __restrict__ out) {
    __shared__ __align__(16) float hs[32 * OC];  // 16 KB
    __shared__ float red[16][4];
    const int tid = threadIdx.x;
    const int warp = tid >> 5, lane = tid & 31;
    const int n0 = blockIdx.x * 32;
    const int cg = tid & 63, rg = tid >> 6;

    // coalesced tile load: 1024 float4 by 512 threads (g_h padded past NN)
    const float4* __restrict__ h4 = (const float4*)(g_h + (size_t)n0 * OC);
    float4* hs4 = (float4*)hs;
    hs4[tid] = h4[tid];
    hs4[tid + 512] = h4[tid + 512];
    __syncthreads();

    const ulonglong2* hq = (const ulonglong2*)hs;  // 32 per node

    ull acc[4][8];
#pragma unroll
    for (int m = 0; m < 4; m++)
#pragma unroll
        for (int j = 0; j < 8; j++) acc[m][j] = 0ull;

    for (int kp = 0; kp < 64; kp += 4) {  // k step 8 over OC=128
        ulonglong2 hv[4][2];
#pragma unroll
        for (int m = 0; m < 4; m++) {
            int base = (rg * 4 + m) * 32 + (kp >> 1);
            hv[m][0] = hq[base];
            hv[m][1] = hq[base + 1];
        }
#pragma unroll
        for (int kp2 = 0; kp2 < 4; kp2++) {
            const ulonglong2* wbase = &g_WpD[(kp + kp2) * 256 + cg];
            ulonglong2 w0 = wbase[0];
            ulonglong2 w1 = wbase[64];
            ulonglong2 w2 = wbase[128];
            ulonglong2 w3 = wbase[192];
#pragma unroll
            for (int m = 0; m < 4; m++) {
                ull xm = (kp2 & 1) ? hv[m][kp2 >> 1].y : hv[m][kp2 >> 1].x;
                fma2(acc[m][0], xm, w0.x);
                fma2(acc[m][1], xm, w0.y);
                fma2(acc[m][2], xm, w1.x);
                fma2(acc[m][3], xm, w1.y);
                fma2(acc[m][4], xm, w2.x);
                fma2(acc[m][5], xm, w2.y);
                fma2(acc[m][6], xm, w3.x);
                fma2(acc[m][7], xm, w3.y);
            }
        }
    }

    float v[4][8];
#pragma unroll
    for (int m = 0; m < 4; m++) {
#pragma unroll
        for (int j = 0; j < 8; j++) {
            float2 p = up2(acc[m][j]);
            v[m][j] = p.x + p.y;
        }
    }

    // softmax: node (rg*4+m)'s 512 cols live in warps rg*2 and rg*2+1
#pragma unroll
    for (int m = 0; m < 4; m++) {
        float lm = v[m][0];
#pragma unroll
        for (int j = 1; j < 8; j++) lm = fmaxf(lm, v[m][j]);
#pragma unroll
        for (int o = 16; o; o >>= 1)
            lm = fmaxf(lm, __shfl_xor_sync(0xffffffffu, lm, o));
        if (lane == 0) red[warp][m] = lm;
    }
    __syncthreads();
    float rm[4];
#pragma unroll
    for (int m = 0; m < 4; m++)
        rm[m] = fmaxf(red[rg * 2][m], red[rg * 2 + 1][m]);
    __syncthreads();

#pragma unroll
    for (int m = 0; m < 4; m++) {
        float ls = 0.f;
#pragma unroll
        for (int j = 0; j < 8; j++) {
            v[m][j] = __expf(v[m][j] - rm[m]);
            ls += v[m][j];
        }
#pragma unroll
        for (int o = 16; o; o >>= 1)
            ls += __shfl_xor_sync(0xffffffffu, ls, o);
        if (lane == 0) red[warp][m] = ls;
    }
    __syncthreads();

#pragma unroll
    for (int m = 0; m < 4; m++) {
        int row = n0 + rg * 4 + m;
        if (row >= NN) continue;
        float inv = 1.f / (red[rg * 2][m] + red[rg * 2 + 1][m]);
        float4* o = (float4*)(out + (size_t)row * IC + cg * 8);
        o[0] = make_float4(v[m][0] * inv, v[m][1] * inv, v[m][2] * inv, v[m][3] * inv);
        o[1] = make_float4(v[m][4] * inv, v[m][5] * inv, v[m][6] * inv, v[m][7] * inv);
    }
}

// ---------------------------------------------------------------------------
extern "C" void kernel_launch(void* const* d_in, const int* in_sizes, int n_in,
                              void* d_out, int out_size) {
    const float* x    = (const float*)d_in[0];
    const int*   ei   = (const int*)d_in[1];
    const float* Wenc = (const float*)d_in[2];
    const float* benc = (const float*)d_in[3];
    const float* Wdec = (const float*)d_in[4];
    float*       out  = (float*)d_out;

    // Side stream + fork/join events, created once on the first (correctness,
    // non-capture) call. Reused every call -> identical work & graph each time.
    static cudaStream_t sB = nullptr;
    static cudaEvent_t evF = nullptr, evJ = nullptr;
    if (sB == nullptr) {
        cudaStreamCreateWithFlags(&sB, cudaStreamNonBlocking);
        cudaEventCreateWithFlags(&evF, cudaEventDisableTiming);
        cudaEventCreateWithFlags(&evJ, cudaEventDisableTiming);
    }

    // fork: stream B builds the CSR while the main stream runs the encode GEMM
    cudaEventRecord(evF, 0);
    cudaStreamWaitEvent(sB, evF, 0);

    // stream B: graph build chain
    k_zero<<<(NN + 255) / 256, 256, 0, sB>>>();
    k_deg<<<(NE + 255) / 256, 256, 0, sB>>>(ei);
    k_bsum<<<NB, 256, 0, sB>>>();
    k_bscan<<<1, 256, 0, sB>>>();
    k_off<<<NB, 256, 0, sB>>>();
    k_scatter<<<(NE + 255) / 256, 256, 0, sB>>>(ei);

    // main stream: weight prep + encode GEMM (independent of graph build)
    k_prep<<<64, 256>>>(Wenc, Wdec);
    k_gemm1<<<(NN + 63) / 64, 256>>>(x);

    // join
    cudaEventRecord(evJ, sB);
    cudaStreamWaitEvent(0, evJ, 0);

    k_gather<<<(NN + 7) / 8, 256>>>(benc);
    k_dec<<<(NN + 31) / 32, 512>>>(out);
}

// round 10
// speedup vs baseline: 1.0517x; 1.0517x over previous
#include <cuda_runtime.h>

#define NN 50000
#define IC 512
#define OC 128
#define NE 1600000
#define NB 196   // scan blocks: 196*256 = 50176 >= NN

typedef unsigned long long ull;

// ---------------------------------------------------------------------------
// Scratch (static __device__ — no allocation in kernel_launch)
__device__ int   g_deg[NN];
__device__ int   g_off[NN + 1];   // CSR row offsets (by dst)
__device__ int   g_cur[NN];       // scatter cursors
__device__ int   g_csrc[NE];      // CSR column = src node per edge
__device__ float g_dis[NN];
__device__ int   g_bsum[NB];      // per-block degree sums
__device__ int   g_bscan[NB + 1]; // exclusive scan of block sums
__device__ float g_y[(size_t)NN * OC];          // x @ W_enc (UNSCALED)
__device__ float g_h[(size_t)(NN + 32) * OC];   // relu(dis*(gather) + b), padded

// k-pair weights, lane-contiguous layout: [kp][j][cg] of ull2.
__device__ ulonglong2 g_WpE[256 * 4 * 16];
__device__ ulonglong2 g_WpD[64 * 4 * 64];

__device__ __forceinline__ void fma2(ull& d, ull a, ull b) {
    asm("fma.rn.f32x2 %0, %1, %2, %0;" : "+l"(d) : "l"(a), "l"(b));
}
__device__ __forceinline__ float2 up2(ull a) {
    float2 r;
    asm("mov.b64 {%0, %1}, %2;" : "=f"(r.x), "=f"(r.y) : "l"(a));
    return r;
}

// ---------------------------------------------------------------------------
// K0: zero deg
__global__ void k_zero() {
    int i = blockIdx.x * blockDim.x + threadIdx.x;
    if (i < NN) g_deg[i] = 0;
}

// K1: dst-degree histogram
__global__ void k_deg(const int* __restrict__ ei) {
    int i = blockIdx.x * blockDim.x + threadIdx.x;
    if (i < NE) atomicAdd(&g_deg[ei[NE + i]], 1);
}

// Scan stage 1: per-block sums of 256 degrees
__global__ __launch_bounds__(256) void k_bsum() {
    __shared__ int ss[8];
    int i = blockIdx.x * 256 + threadIdx.x;
    int v = (i < NN) ? g_deg[i] : 0;
#pragma unroll
    for (int o = 16; o; o >>= 1) v += __shfl_xor_sync(0xffffffffu, v, o);
    if ((threadIdx.x & 31) == 0) ss[threadIdx.x >> 5] = v;
    __syncthreads();
    if (threadIdx.x == 0) {
        int s = 0;
#pragma unroll
        for (int w = 0; w < 8; w++) s += ss[w];
        g_bsum[blockIdx.x] = s;
    }
}

// Scan stage 2: one block exclusive-scans NB block sums
__global__ __launch_bounds__(256) void k_bscan() {
    __shared__ int sc[256];
    int t = threadIdx.x;
    int v = (t < NB) ? g_bsum[t] : 0;
    sc[t] = v;
    __syncthreads();
    for (int off = 1; off < 256; off <<= 1) {
        int u = (t >= off) ? sc[t - off] : 0;
        __syncthreads();
        sc[t] += u;
        __syncthreads();
    }
    if (t < NB) g_bscan[t] = sc[t] - v;   // exclusive
    if (t == NB - 1) g_bscan[NB] = sc[t];
}

// Scan stage 3: per-block scan of degrees + global base -> off/cur/dis
__global__ __launch_bounds__(256) void k_off() {
    __shared__ int sc[256];
    int t = threadIdx.x;
    int i = blockIdx.x * 256 + t;
    int d = (i < NN) ? g_deg[i] : 0;
    sc[t] = d;
    __syncthreads();
    for (int off = 1; off < 256; off <<= 1) {
        int u = (t >= off) ? sc[t - off] : 0;
        __syncthreads();
        sc[t] += u;
        __syncthreads();
    }
    if (i < NN) {
        int base = g_bscan[blockIdx.x] + sc[t] - d;  // exclusive
        g_off[i] = base;
        g_cur[i] = base;
        g_dis[i] = rsqrtf((float)(d + 1));
        if (i == NN - 1) g_off[NN] = base + d;
    }
}

// K3: scatter edges into CSR (order within a row is irrelevant for a sum)
__global__ void k_scatter(const int* __restrict__ ei) {
    int i = blockIdx.x * blockDim.x + threadIdx.x;
    if (i >= NE) return;
    int s = ei[i];
    int d = ei[NE + i];
    int p = atomicAdd(&g_cur[d], 1);
    g_csrc[p] = s;
}

// K_prep: build lane-contiguous k-pair weight layouts
__global__ void k_prep(const float* __restrict__ We, const float* __restrict__ Wd) {
    int i = blockIdx.x * blockDim.x + threadIdx.x;
    if (i < 256 * 4 * 16) {  // enc
        int kp = i >> 6, j = (i >> 4) & 3, cg = i & 15;
        int c = cg * 8 + 2 * j;
        float4 v;
        v.x = We[(2 * kp) * OC + c];
        v.y = We[(2 * kp + 1) * OC + c];
        v.z = We[(2 * kp) * OC + c + 1];
        v.w = We[(2 * kp + 1) * OC + c + 1];
        ((float4*)g_WpE)[i] = v;
    }
    if (i < 64 * 4 * 64) {  // dec
        int kp = i >> 8, j = (i >> 6) & 3, cg = i & 63;
        int c = cg * 8 + 2 * j;
        float4 v;
        v.x = Wd[(2 * kp) * IC + c];
        v.y = Wd[(2 * kp + 1) * IC + c];
        v.z = Wd[(2 * kp) * IC + c + 1];
        v.w = Wd[(2 * kp + 1) * IC + c + 1];
        ((float4*)g_WpD)[i] = v;
    }
}

// ---------------------------------------------------------------------------
// K4: y = x @ W_enc (UNSCALED) via packed f32x2 FMA, K-paired.
// 64 rows/block, 256 threads. No dependency on graph build -> overlappable.
__global__ __launch_bounds__(256) void k_gemm1(const float* __restrict__ x) {
    const int tid = threadIdx.x;
    const int warp = tid >> 5, lane = tid & 31;
    const int cg = lane & 15, rg = lane >> 4;
    const int row0 = blockIdx.x * 64 + warp * 8 + rg * 4;

    const ulonglong2* __restrict__ xq = (const ulonglong2*)x;

    int r[4];
#pragma unroll
    for (int m = 0; m < 4; m++) r[m] = min(row0 + m, NN - 1);

    ull acc[4][8];
#pragma unroll
    for (int m = 0; m < 4; m++)
#pragma unroll
        for (int j = 0; j < 8; j++) acc[m][j] = 0ull;

    for (int kp = 0; kp < 256; kp += 4) {
        ulonglong2 xv[4][2];
#pragma unroll
        for (int m = 0; m < 4; m++) {
            size_t base = (size_t)r[m] * 128 + (kp >> 1);
            xv[m][0] = xq[base];
            xv[m][1] = xq[base + 1];
        }
#pragma unroll
        for (int kp2 = 0; kp2 < 4; kp2++) {
            const ulonglong2* wbase = &g_WpE[(kp + kp2) * 64 + cg];
            ulonglong2 w0 = wbase[0];
            ulonglong2 w1 = wbase[16];
            ulonglong2 w2 = wbase[32];
            ulonglong2 w3 = wbase[48];
#pragma unroll
            for (int m = 0; m < 4; m++) {
                ull xm = (kp2 & 1) ? xv[m][kp2 >> 1].y : xv[m][kp2 >> 1].x;
                fma2(acc[m][0], xm, w0.x);
                fma2(acc[m][1], xm, w0.y);
                fma2(acc[m][2], xm, w1.x);
                fma2(acc[m][3], xm, w1.y);
                fma2(acc[m][4], xm, w2.x);
                fma2(acc[m][5], xm, w2.y);
                fma2(acc[m][6], xm, w3.x);
                fma2(acc[m][7], xm, w3.y);
            }
        }
    }

#pragma unroll
    for (int m = 0; m < 4; m++) {
        int row = row0 + m;
        if (row >= NN) continue;
        float v[8];
#pragma unroll
        for (int j = 0; j < 8; j++) {
            float2 p = up2(acc[m][j]);
            v[j] = p.x + p.y;
        }
        float4* o = (float4*)(g_y + (size_t)row * OC + cg * 8);
        o[0] = make_float4(v[0], v[1], v[2], v[3]);
        o[1] = make_float4(v[4], v[5], v[6], v[7]);
    }
}

// ---------------------------------------------------------------------------
// K5: gather + epilogue, one warp per node, high occupancy.
// h[n] = relu(dis[n]*(y[n]*dis[n] + sum_{src} y[src]*dis[src]) + b)
__global__ __launch_bounds__(256) void k_gather(const float* __restrict__ b) {
    const int warp = blockIdx.x * 8 + (threadIdx.x >> 5);
    if (warp >= NN) return;
    const int lane = threadIdx.x & 31;
    const int n = warp;

    const float4* __restrict__ y4 = (const float4*)g_y;

    float dn = g_dis[n];
    float4 a = y4[(size_t)n * 32 + lane];  // self loop: y[n] * dis[n]
    a.x *= dn; a.y *= dn; a.z *= dn; a.w *= dn;

    int e = g_off[n], end = g_off[n + 1];
    for (; e + 4 <= end; e += 4) {
        int s0 = g_csrc[e],     s1 = g_csrc[e + 1];
        int s2 = g_csrc[e + 2], s3 = g_csrc[e + 3];
        float d0 = g_dis[s0], d1 = g_dis[s1];
        float d2 = g_dis[s2], d3 = g_dis[s3];
        float4 v0 = y4[(size_t)s0 * 32 + lane];
        float4 v1 = y4[(size_t)s1 * 32 + lane];
        float4 v2 = y4[(size_t)s2 * 32 + lane];
        float4 v3 = y4[(size_t)s3 * 32 + lane];
        a.x = fmaf(v0.x, d0, a.x); a.y = fmaf(v0.y, d0, a.y);
        a.z = fmaf(v0.z, d0, a.z); a.w = fmaf(v0.w, d0, a.w);
        a.x = fmaf(v1.x, d1, a.x); a.y = fmaf(v1.y, d1, a.y);
        a.z = fmaf(v1.z, d1, a.z); a.w = fmaf(v1.w, d1, a.w);
        a.x = fmaf(v2.x, d2, a.x); a.y = fmaf(v2.y, d2, a.y);
        a.z = fmaf(v2.z, d2, a.z); a.w = fmaf(v2.w, d2, a.w);
        a.x = fmaf(v3.x, d3, a.x); a.y = fmaf(v3.y, d3, a.y);
        a.z = fmaf(v3.z, d3, a.z); a.w = fmaf(v3.w, d3, a.w);
    }
    for (; e < end; e++) {
        int s = g_csrc[e];
        float ds = g_dis[s];
        float4 v = y4[(size_t)s * 32 + lane];
        a.x = fmaf(v.x, ds, a.x); a.y = fmaf(v.y, ds, a.y);
        a.z = fmaf(v.z, ds, a.z); a.w = fmaf(v.w, ds, a.w);
    }
    const float4 b4 = ((const float4*)b)[lane];
    float4 h;
    h.x = fmaxf(fmaf(dn, a.x, b4.x), 0.f);
    h.y = fmaxf(fmaf(dn, a.y, b4.y), 0.f);
    h.z = fmaxf(fmaf(dn, a.z, b4.z), 0.f);
    h.w = fmaxf(fmaf(dn, a.w, b4.w), 0.f);
    ((float4*)g_h)[(size_t)n * 32 + lane] = h;
}

// ---------------------------------------------------------------------------
// K6: decode GEMM (f32x2, K-paired) + softmax from precomputed h.
// 16 nodes/block, 256 threads. cg = tid&63 -> cols cg*8..+7; rg = tid>>6.
__global__ __launch_bounds__(256) void k_dec(float* __restrict__ out) {
    __shared__ __align__(16) float hs[16 * OC];  // 8 KB
    __shared__ float red[8][4];
    const int tid = threadIdx.x;
    const int warp = tid >> 5, lane = tid & 31;
    const int n0 = blockIdx.x * 16;
    const int cg = tid & 63, rg = tid >> 6;

    // coalesced tile load: 512 float4 by 256 threads
    const float4* __restrict__ h4 = (const float4*)(g_h + (size_t)n0 * OC);
    float4* hs4 = (float4*)hs;
    hs4[tid] = h4[tid];
    hs4[tid + 256] = h4[tid + 256];
    __syncthreads();

    const ulonglong2* hq = (const ulonglong2*)hs;  // 32 per node

    ull acc[4][8];
#pragma unroll
    for (int m = 0; m < 4; m++)
#pragma unroll
        for (int j = 0; j < 8; j++) acc[m][j] = 0ull;

    for (int kp = 0; kp < 64; kp += 4) {  // k step 8 over OC=128
        ulonglong2 hv[4][2];
#pragma unroll
        for (int m = 0; m < 4; m++) {
            int base = (rg * 4 + m) * 32 + (kp >> 1);
            hv[m][0] = hq[base];
            hv[m][1] = hq[base + 1];
        }
#pragma unroll
        for (int kp2 = 0; kp2 < 4; kp2++) {
            const ulonglong2* wbase = &g_WpD[(kp + kp2) * 256 + cg];
            ulonglong2 w0 = wbase[0];
            ulonglong2 w1 = wbase[64];
            ulonglong2 w2 = wbase[128];
            ulonglong2 w3 = wbase[192];
#pragma unroll
            for (int m = 0; m < 4; m++) {
                ull xm = (kp2 & 1) ? hv[m][kp2 >> 1].y : hv[m][kp2 >> 1].x;
                fma2(acc[m][0], xm, w0.x);
                fma2(acc[m][1], xm, w0.y);
                fma2(acc[m][2], xm, w1.x);
                fma2(acc[m][3], xm, w1.y);
                fma2(acc[m][4], xm, w2.x);
                fma2(acc[m][5], xm, w2.y);
                fma2(acc[m][6], xm, w3.x);
                fma2(acc[m][7], xm, w3.y);
            }
        }
    }

    float v[4][8];
#pragma unroll
    for (int m = 0; m < 4; m++) {
#pragma unroll
        for (int j = 0; j < 8; j++) {
            float2 p = up2(acc[m][j]);
            v[m][j] = p.x + p.y;
        }
    }

    // softmax: node (rg*4+m)'s 512 cols live in warps rg*2 and rg*2+1
#pragma unroll
    for (int m = 0; m < 4; m++) {
        float lm = v[m][0];
#pragma unroll
        for (int j = 1; j < 8; j++) lm = fmaxf(lm, v[m][j]);
#pragma unroll
        for (int o = 16; o; o >>= 1)
            lm = fmaxf(lm, __shfl_xor_sync(0xffffffffu, lm, o));
        if (lane == 0) red[warp][m] = lm;
    }
    __syncthreads();
    float rm[4];
#pragma unroll
    for (int m = 0; m < 4; m++)
        rm[m] = fmaxf(red[rg * 2][m], red[rg * 2 + 1][m]);
    __syncthreads();

#pragma unroll
    for (int m = 0; m < 4; m++) {
        float ls = 0.f;
#pragma unroll
        for (int j = 0; j < 8; j++) {
            v[m][j] = __expf(v[m][j] - rm[m]);
            ls += v[m][j];
        }
#pragma unroll
        for (int o = 16; o; o >>= 1)
            ls += __shfl_xor_sync(0xffffffffu, ls, o);
        if (lane == 0) red[warp][m] = ls;
    }
    __syncthreads();

#pragma unroll
    for (int m = 0; m < 4; m++) {
        float inv = 1.f / (red[rg * 2][m] + red[rg * 2 + 1][m]);
        int row = n0 + rg * 4 + m;
        float4* o = (float4*)(out + (size_t)row * IC + cg * 8);
        o[0] = make_float4(v[m][0] * inv, v[m][1] * inv, v[m][2] * inv, v[m][3] * inv);
        o[1] = make_float4(v[m][4] * inv, v[m][5] * inv, v[m][6] * inv, v[m][7] * inv);
    }
}

// ---------------------------------------------------------------------------
extern "C" void kernel_launch(void* const* d_in, const int* in_sizes, int n_in,
                              void* d_out, int out_size) {
    const float* x    = (const float*)d_in[0];
    const int*   ei   = (const int*)d_in[1];
    const float* Wenc = (const float*)d_in[2];
    const float* benc = (const float*)d_in[3];
    const float* Wdec = (const float*)d_in[4];
    float*       out  = (float*)d_out;

    // Side stream + fork/join events, created once on the first (correctness,
    // non-capture) call. Reused every call -> identical work & graph each time.
    static cudaStream_t sB = nullptr;
    static cudaEvent_t evF = nullptr, evJ = nullptr;
    if (sB == nullptr) {
        cudaStreamCreateWithFlags(&sB, cudaStreamNonBlocking);
        cudaEventCreateWithFlags(&evF, cudaEventDisableTiming);
        cudaEventCreateWithFlags(&evJ, cudaEventDisableTiming);
    }

    // fork: stream B builds the CSR while the main stream runs the encode GEMM
    cudaEventRecord(evF, 0);
    cudaStreamWaitEvent(sB, evF, 0);

    // stream B: graph build chain
    k_zero<<<(NN + 255) / 256, 256, 0, sB>>>();
    k_deg<<<(NE + 255) / 256, 256, 0, sB>>>(ei);
    k_bsum<<<NB, 256, 0, sB>>>();
    k_bscan<<<1, 256, 0, sB>>>();
    k_off<<<NB, 256, 0, sB>>>();
    k_scatter<<<(NE + 255) / 256, 256, 0, sB>>>(ei);

    // main stream: weight prep + encode GEMM (independent of graph build)
    k_prep<<<64, 256>>>(Wenc, Wdec);
    k_gemm1<<<(NN + 63) / 64, 256>>>(x);

    // join
    cudaEventRecord(evJ, sB);
    cudaStreamWaitEvent(0, evJ, 0);

    k_gather<<<(NN + 7) / 8, 256>>>(benc);
    k_dec<<<NN / 16, 256>>>(out);
}